// round 5
// baseline (speedup 1.0000x reference)
#include <cuda_runtime.h>
#include <math.h>
#include <stdint.h>

#define NB 8192
#define KN 32
#define HD 1024
#define ROWS_PER_STAGE 8
#define STAGE_FLOATS (ROWS_PER_STAGE * HD)      // 8192 floats
#define STAGE_BYTES  (STAGE_FLOATS * 4)         // 32 KB
#define NSTAGES      (KN / ROWS_PER_STAGE)      // 4
#define DYN_SMEM_BYTES ((2 * STAGE_FLOATS + HD) * 4)   // 69632

__device__ __forceinline__ uint32_t smem_u32(const void* p) {
    return (uint32_t)__cvta_generic_to_shared(p);
}
__device__ __forceinline__ void mbar_init(uint32_t mbar, uint32_t count) {
    asm volatile("mbarrier.init.shared::cta.b64 [%0], %1;"
                 :: "r"(mbar), "r"(count) : "memory");
}
__device__ __forceinline__ void mbar_expect_tx(uint32_t mbar, uint32_t bytes) {
    asm volatile("mbarrier.arrive.expect_tx.shared::cta.b64 _, [%0], %1;"
                 :: "r"(mbar), "r"(bytes) : "memory");
}
__device__ __forceinline__ void bulk_g2s(uint32_t dst, const void* src,
                                         uint32_t bytes, uint32_t mbar) {
    asm volatile(
        "cp.async.bulk.shared::cta.global.mbarrier::complete_tx::bytes "
        "[%0], [%1], %2, [%3];"
        :: "r"(dst), "l"(src), "r"(bytes), "r"(mbar) : "memory");
}
__device__ __forceinline__ void mbar_wait(uint32_t mbar, uint32_t phase) {
    uint32_t done;
    do {
        asm volatile(
            "{\n\t.reg .pred p;\n\t"
            "mbarrier.try_wait.parity.acquire.cta.shared::cta.b64 p, [%1], %2, 0x989680;\n\t"
            "selp.b32 %0, 1, 0, p;\n\t}"
            : "=r"(done) : "r"(mbar), "r"(phase) : "memory");
    } while (!done);
}

__global__ __launch_bounds__(256, 3)
void mu_calc_kernel(
    const int*   __restrict__ vals,
    const float* __restrict__ distances,
    const float* __restrict__ cache_hidden,
    const float* __restrict__ hiddens,
    const float* __restrict__ W1,
    const float* __restrict__ b1,
    const float* __restrict__ W2,
    const float* __restrict__ b2,
    float*       __restrict__ out)
{
    extern __shared__ __align__(16) float dyn[];
    float* s_buf   = dyn;                        // 2 stages * 8192 floats (64 KB)
    float* s_cache = dyn + 2 * STAGE_FLOATS;     // 1024 floats (4 KB)

    __shared__ float s_cd[KN];
    __shared__ float s_x[96];
    __shared__ int   s_vals[KN];
    __shared__ float s_h2[64];
    __shared__ float s_scale;
    __shared__ __align__(8) unsigned long long s_mbar[2];

    const int b    = blockIdx.x;
    const int tid  = threadIdx.x;
    const int warp = tid >> 5;
    const int lane = tid & 31;

    const uint32_t mb0 = smem_u32(&s_mbar[0]);
    const uint32_t mb1 = smem_u32(&s_mbar[1]);
    const uint32_t buf0 = smem_u32(s_buf);
    const uint32_t buf1 = buf0 + STAGE_BYTES;

    // ---- stage small per-batch data (overlaps with mbar init) ----
    const float4* ch4 = reinterpret_cast<const float4*>(cache_hidden + (size_t)b * HD);
    reinterpret_cast<float4*>(s_cache)[tid] = ch4[tid];       // 256 * 16B = 4KB
    if (tid < KN) {
        s_vals[tid]   = vals[b * KN + tid];
        s_x[32 + tid] = distances[b * KN + tid];
    }
    if (tid == 0) {
        mbar_init(mb0, 1);
        mbar_init(mb1, 1);
        asm volatile("fence.proxy.async.shared::cta;" ::: "memory");
    }
    __syncthreads();

    const float* gsrc = hiddens + (size_t)b * KN * HD;

    // ---- kick off the first two TMA stages ----
    if (tid == 0) {
        mbar_expect_tx(mb0, STAGE_BYTES);
        bulk_g2s(buf0, gsrc, STAGE_BYTES, mb0);
        mbar_expect_tx(mb1, STAGE_BYTES);
        bulk_g2s(buf1, gsrc + STAGE_FLOATS, STAGE_BYTES, mb1);
    }

    // cache row -> registers (reused across all stages; no LDS in hot loop)
    const float4* sc4 = reinterpret_cast<const float4*>(s_cache);
    float4 cv[8];
    #pragma unroll
    for (int i = 0; i < 8; i++) cv[i] = sc4[lane + 32 * i];

    // ---- pipelined consume: each warp reduces one 4KB row per stage ----
    for (int s = 0; s < NSTAGES; s++) {
        const int bb = s & 1;
        mbar_wait(bb ? mb1 : mb0, s >> 1);

        const float4* row = reinterpret_cast<const float4*>(
            s_buf + bb * STAGE_FLOATS + warp * HD);
        float acc = 0.f;
        #pragma unroll
        for (int i = 0; i < 8; i++) {
            const float4 h = row[lane + 32 * i];
            const float4 c = cv[i];
            float d;
            d = c.x - h.x; acc = fmaf(d, d, acc);
            d = c.y - h.y; acc = fmaf(d, d, acc);
            d = c.z - h.z; acc = fmaf(d, d, acc);
            d = c.w - h.w; acc = fmaf(d, d, acc);
        }
        #pragma unroll
        for (int o = 16; o > 0; o >>= 1)
            acc += __shfl_xor_sync(0xffffffffu, acc, o);
        if (lane == 0) s_cd[s * ROWS_PER_STAGE + warp] = sqrtf(acc);

        __syncthreads();   // all warps done reading buf[bb]
        if (tid == 0 && s + 2 < NSTAGES) {
            const uint32_t m = bb ? mb1 : mb0;
            mbar_expect_tx(m, STAGE_BYTES);
            bulk_g2s(bb ? buf1 : buf0, gsrc + (size_t)(s + 2) * STAGE_FLOATS,
                     STAGE_BYTES, m);
        }
    }

    // ---- label counts (warp 0) + assemble x ----
    if (warp == 0) {
        const int v = s_vals[lane];
        int flag = (v != 0) ? 1 : 0;
        for (int j = 0; j < lane; j++)
            if (s_vals[j] == v) flag = 0;
        int c = flag;
        #pragma unroll
        for (int o = 1; o < 32; o <<= 1) {
            int t = __shfl_up_sync(0xffffffffu, c, o);
            if (lane >= o) c += t;
        }
        s_x[64 + lane] = (float)c;
        s_x[lane]      = s_cd[lane];
    }
    __syncthreads();

    // ---- MLP 96 -> 64 -> 1 ----
    if (tid < 64) {
        const float* w = W1 + tid * 96;   // 24KB: L2-resident across all CTAs
        float a = b1[tid];
        #pragma unroll
        for (int i = 0; i < 96; i++)
            a = fmaf(s_x[i], __ldg(w + i), a);
        s_h2[tid] = tanhf(a) * __ldg(W2 + tid);
    }
    __syncthreads();
    if (tid == 0) {
        float s = b2[0];
        #pragma unroll
        for (int i = 0; i < 64; i++) s += s_h2[i];
        s_scale = 5.0f / (1.0f + expf(-s));
    }
    __syncthreads();

    // ---- write outputs (concat: context_dist | new_distances) ----
    if (tid < KN) {
        const float cd = s_cd[tid] * s_scale;
        out[(size_t)b * KN + tid]                   = cd;
        out[(size_t)NB * KN + (size_t)b * KN + tid] = s_x[32 + tid] + cd;
    }
}

extern "C" void kernel_launch(void* const* d_in, const int* in_sizes, int n_in,
                              void* d_out, int out_size) {
    const int*   vals         = (const int*)  d_in[0];
    const float* distances    = (const float*)d_in[1];
    const float* cache_hidden = (const float*)d_in[2];
    const float* hiddens      = (const float*)d_in[3];
    const float* W1           = (const float*)d_in[4];
    const float* b1           = (const float*)d_in[5];
    const float* W2           = (const float*)d_in[6];
    const float* b2           = (const float*)d_in[7];
    float* out = (float*)d_out;

    static int attr_set = 0;
    if (!attr_set) {
        cudaFuncSetAttribute(mu_calc_kernel,
                             cudaFuncAttributeMaxDynamicSharedMemorySize,
                             DYN_SMEM_BYTES);
        attr_set = 1;
    }
    mu_calc_kernel<<<NB, 256, DYN_SMEM_BYTES>>>(vals, distances, cache_hidden,
                                                hiddens, W1, b1, W2, b2, out);
}

// round 6
// speedup vs baseline: 1.0251x; 1.0251x over previous
#include <cuda_runtime.h>
#include <math.h>
#include <stdint.h>

#define NB 8192
#define KN 32
#define HD 1024
#define GRID 444                                 // 148 SMs * 3 CTAs, one wave
#define ROWS_PER_STAGE 8
#define STAGE_FLOATS (ROWS_PER_STAGE * HD)       // 8192 floats
#define STAGE_BYTES  (STAGE_FLOATS * 4)          // 32 KB
#define DYN_SMEM_BYTES ((2 * STAGE_FLOATS + 2 * HD) * 4)   // 64KB buf + 8KB cache = 73728

__device__ __forceinline__ uint32_t smem_u32(const void* p) {
    return (uint32_t)__cvta_generic_to_shared(p);
}
__device__ __forceinline__ void mbar_init(uint32_t mbar, uint32_t count) {
    asm volatile("mbarrier.init.shared::cta.b64 [%0], %1;"
                 :: "r"(mbar), "r"(count) : "memory");
}
__device__ __forceinline__ void mbar_expect_tx(uint32_t mbar, uint32_t bytes) {
    asm volatile("mbarrier.arrive.expect_tx.shared::cta.b64 _, [%0], %1;"
                 :: "r"(mbar), "r"(bytes) : "memory");
}
__device__ __forceinline__ void bulk_g2s(uint32_t dst, const void* src,
                                         uint32_t bytes, uint32_t mbar) {
    asm volatile(
        "cp.async.bulk.shared::cta.global.mbarrier::complete_tx::bytes "
        "[%0], [%1], %2, [%3];"
        :: "r"(dst), "l"(src), "r"(bytes), "r"(mbar) : "memory");
}
__device__ __forceinline__ void mbar_wait(uint32_t mbar, uint32_t phase) {
    uint32_t done;
    do {
        asm volatile(
            "{\n\t.reg .pred p;\n\t"
            "mbarrier.try_wait.parity.acquire.cta.shared::cta.b64 p, [%1], %2, 0x989680;\n\t"
            "selp.b32 %0, 1, 0, p;\n\t}"
            : "=r"(done) : "r"(mbar), "r"(phase) : "memory");
    } while (!done);
}

__global__ __launch_bounds__(256, 3)
void mu_calc_kernel(
    const int*   __restrict__ vals,
    const float* __restrict__ distances,
    const float* __restrict__ cache_hidden,
    const float* __restrict__ hiddens,
    const float* __restrict__ W1,
    const float* __restrict__ b1,
    const float* __restrict__ W2,
    const float* __restrict__ b2,
    float*       __restrict__ out)
{
    extern __shared__ __align__(16) float dyn[];
    float* s_buf   = dyn;                        // 2 stage buffers (64 KB)
    float* s_cache = dyn + 2 * STAGE_FLOATS;     // 2 cache_hidden slots (8 KB)

    __shared__ float s_cd[KN];
    __shared__ float s_x[96];
    __shared__ int   s_vals[KN];
    __shared__ float s_h2[64];
    __shared__ float s_scale;
    __shared__ __align__(8) unsigned long long s_mbar[2];

    const int tid  = threadIdx.x;
    const int warp = tid >> 5;
    const int lane = tid & 31;

    const uint32_t mb0  = smem_u32(&s_mbar[0]);
    const uint32_t mb1  = smem_u32(&s_mbar[1]);
    const uint32_t buf0 = smem_u32(s_buf);
    const uint32_t buf1 = buf0 + STAGE_BYTES;

    const int b0 = blockIdx.x;
    const int nb = (NB - b0 + GRID - 1) / GRID;       // batches owned by this CTA
    const int TOT = 4 * nb;                            // global stage count

    // ---- init: mbarriers + cache slot 0 for first batch ----
    if (tid == 0) {
        mbar_init(mb0, 1);
        mbar_init(mb1, 1);
        asm volatile("fence.proxy.async.shared::cta;" ::: "memory");
    }
    reinterpret_cast<float4*>(s_cache)[tid] =
        reinterpret_cast<const float4*>(cache_hidden + (size_t)b0 * HD)[tid];
    __syncthreads();

    // ---- prime the global stage pipeline (stages 0,1 of batch 0) ----
    if (tid == 0) {
        const float* src0 = hiddens + (size_t)b0 * KN * HD;
        mbar_expect_tx(mb0, STAGE_BYTES);
        bulk_g2s(buf0, src0, STAGE_BYTES, mb0);
        mbar_expect_tx(mb1, STAGE_BYTES);
        bulk_g2s(buf1, src0 + STAGE_FLOATS, STAGE_BYTES, mb1);
    }

    for (int i = 0; i < nb; i++) {
        const int b = b0 + i * GRID;

        // small per-batch inputs
        if (tid < KN) {
            s_vals[tid]   = vals[b * KN + tid];
            s_x[32 + tid] = distances[b * KN + tid];
        }

        // cache row -> registers (slot i&1)
        const float4* sc4 = reinterpret_cast<const float4*>(s_cache + (i & 1) * HD);
        float4 cv[8];
        #pragma unroll
        for (int j = 0; j < 8; j++) cv[j] = sc4[lane + 32 * j];

        // kick prefetch of NEXT batch's cache row (lands during stage loop)
        float4 cnext;
        const bool hasnext = (i + 1 < nb);
        if (hasnext)
            cnext = reinterpret_cast<const float4*>(
                cache_hidden + (size_t)(b + GRID) * HD)[tid];

        // ---- 4 stages; pipeline runs ACROSS batch boundaries ----
        for (int s = 0; s < 4; s++) {
            const int g  = 4 * i + s;
            const int bb = g & 1;
            mbar_wait(bb ? mb1 : mb0, (g >> 1) & 1);

            const float4* row = reinterpret_cast<const float4*>(
                s_buf + bb * STAGE_FLOATS + warp * HD);
            float acc = 0.f;
            #pragma unroll
            for (int j = 0; j < 8; j++) {
                const float4 h = row[lane + 32 * j];
                const float4 c = cv[j];
                float d;
                d = c.x - h.x; acc = fmaf(d, d, acc);
                d = c.y - h.y; acc = fmaf(d, d, acc);
                d = c.z - h.z; acc = fmaf(d, d, acc);
                d = c.w - h.w; acc = fmaf(d, d, acc);
            }
            #pragma unroll
            for (int o = 16; o > 0; o >>= 1)
                acc += __shfl_xor_sync(0xffffffffu, acc, o);
            if (lane == 0) s_cd[s * ROWS_PER_STAGE + warp] = sqrtf(acc);

            __syncthreads();   // all warps done with buf[bb]

            const int gn = g + 2;
            if (tid == 0 && gn < TOT) {
                const int bi = b0 + (gn >> 2) * GRID;
                const float* src = hiddens +
                    ((size_t)bi * KN + (size_t)(gn & 3) * ROWS_PER_STAGE) * HD;
                const uint32_t m = (gn & 1) ? mb1 : mb0;
                mbar_expect_tx(m, STAGE_BYTES);
                bulk_g2s((gn & 1) ? buf1 : buf0, src, STAGE_BYTES, m);
            }
        }

        // store next batch's cache row (visibility covered by tail syncs)
        if (hasnext)
            reinterpret_cast<float4*>(s_cache + ((i + 1) & 1) * HD)[tid] = cnext;

        // ---- tail: labels + MLP + outputs (TMA keeps streaming meanwhile) ----
        if (warp == 0) {
            const int v = s_vals[lane];
            int flag = (v != 0) ? 1 : 0;
            for (int j = 0; j < lane; j++)
                if (s_vals[j] == v) flag = 0;
            int c = flag;
            #pragma unroll
            for (int o = 1; o < 32; o <<= 1) {
                int t = __shfl_up_sync(0xffffffffu, c, o);
                if (lane >= o) c += t;
            }
            s_x[64 + lane] = (float)c;
            s_x[lane]      = s_cd[lane];
        }
        __syncthreads();

        if (tid < 64) {
            const float* w = W1 + tid * 96;   // 24KB: L2-resident
            float a = b1[tid];
            #pragma unroll
            for (int j = 0; j < 96; j++)
                a = fmaf(s_x[j], __ldg(w + j), a);
            s_h2[tid] = tanhf(a) * __ldg(W2 + tid);
        }
        __syncthreads();

        if (warp == 0) {
            float v = s_h2[lane] + s_h2[lane + 32];
            #pragma unroll
            for (int o = 16; o > 0; o >>= 1)
                v += __shfl_xor_sync(0xffffffffu, v, o);
            if (lane == 0) {
                const float s = v + b2[0];
                s_scale = 5.0f / (1.0f + expf(-s));
            }
        }
        __syncthreads();

        if (tid < KN) {
            const float cd = s_cd[tid] * s_scale;
            out[(size_t)b * KN + tid]                   = cd;
            out[(size_t)NB * KN + (size_t)b * KN + tid] = s_x[32 + tid] + cd;
        }
        __syncthreads();   // protect s_cd/s_x/s_cache before next batch
    }
}

extern "C" void kernel_launch(void* const* d_in, const int* in_sizes, int n_in,
                              void* d_out, int out_size) {
    const int*   vals         = (const int*)  d_in[0];
    const float* distances    = (const float*)d_in[1];
    const float* cache_hidden = (const float*)d_in[2];
    const float* hiddens      = (const float*)d_in[3];
    const float* W1           = (const float*)d_in[4];
    const float* b1           = (const float*)d_in[5];
    const float* W2           = (const float*)d_in[6];
    const float* b2           = (const float*)d_in[7];
    float* out = (float*)d_out;

    static int attr_set = 0;
    if (!attr_set) {
        cudaFuncSetAttribute(mu_calc_kernel,
                             cudaFuncAttributeMaxDynamicSharedMemorySize,
                             DYN_SMEM_BYTES);
        attr_set = 1;
    }
    mu_calc_kernel<<<GRID, 256, DYN_SMEM_BYTES>>>(vals, distances, cache_hidden,
                                                  hiddens, W1, b1, W2, b2, out);
}